// round 14
// baseline (speedup 1.0000x reference)
#include <cuda_runtime.h>
#include <math.h>
#include <stdint.h>

#define Bn 64
#define Pn 25200
#define Gn 48
#define NB3 99            // ceil(Pn/256)
#define NTH 256
#define NTHB 1024         // k_batch threads
#define KPT 25            // ce values per thread in k_batch (25*1024 >= 25200)

// ---------------- scratch (no allocations allowed) ----------------
__device__ unsigned long long d_gpart[Bn*Gn*NB3]; // per-(b,g,chunk) partial argmax keys
__device__ unsigned d_bpi[Bn*Gn];            // best prior index per gt
__device__ unsigned long long d_vmask[Bn];   // valid-gt bitmask per batch
__device__ unsigned long long d_cmask[Bn*NB3]; // per-(batch,chunk) gt-index mask
__device__ float2 d_povg[Bn*Pn];             // per-prior (exact ov, bg as int bits)
__device__ float  d_ce[Bn*Pn];               // ce for non-pos, -1 for pos
__device__ int    d_hv[Bn];                  // has_valid per batch
__device__ float  d_part_ll[Bn*NB3];
__device__ float  d_part_lm[Bn*NB3];
__device__ float  d_part_pce[Bn*NB3];
__device__ int    d_part_np[Bn*NB3];         // np | (np1<<16)
__device__ double d_b_ll[Bn], d_b_lm[Bn], d_b_lc[Bn];
__device__ int    d_b_np[Bn], d_b_np1[Bn];

// ---------------- helpers ----------------
__device__ __forceinline__ float sl1(float d) {
    d = fabsf(d);
    return d < 1.0f ? 0.5f * d * d : d - 0.5f;
}

__device__ __forceinline__ float inter_fn(float4 t, float4 pf) {
    float ltx = fmaxf(t.x, pf.x), lty = fmaxf(t.y, pf.y);
    float rbx = fminf(t.z, pf.z), rby = fminf(t.w, pf.w);
    float iw = fmaxf(rbx - ltx, 0.0f), ih = fmaxf(rby - lty, 0.0f);
    return iw * ih;
}

// ---------------- KA: single-pass IoU, dual argmax (no prep kernel) --------------
__global__ void k_A(const int* __restrict__ gnum_arr, const float* __restrict__ priors,
                    const float* __restrict__ gtb, const int* __restrict__ img) {
    __shared__ float4 str[Gn];
    __shared__ float  sa[Gn];
    __shared__ unsigned long long swk[Gn][8];
    int b = blockIdx.y, chunk = blockIdx.x;
    int tid = threadIdx.x, lane = tid & 31, wid = tid >> 5;

    float w = (float)img[b * 2 + 1];
    float h = (float)img[b * 2 + 0];
    if (tid < Gn * 4)
        ((float*)str)[tid] = gtb[b * Gn * 4 + tid] / ((tid & 1) ? h : w);
    if (tid < Gn) {
        float x1 = gtb[b*Gn*4 + tid*4+0] / w, y1 = gtb[b*Gn*4 + tid*4+1] / h;
        float x2 = gtb[b*Gn*4 + tid*4+2] / w, y2 = gtb[b*Gn*4 + tid*4+3] / h;
        sa[tid] = (x2 - x1) * (y2 - y1);
    }
    if (tid == 0) {
        d_cmask[b * NB3 + chunk] = 0ull;          // zeroed before B's atomicOr
        if (chunk == 0) { d_vmask[b] = 0ull; d_hv[b] = 0; }
    }
    __syncthreads();

    int gnum = min(gnum_arr[b], Gn);
    int p = chunk * NTH + tid;
    float4 pf;
    if (p < Pn) {
        float4 pr = ((const float4*)priors)[p];
        float hx = pr.z * 0.5f, hy = pr.w * 0.5f;
        pf.x = pr.x - hx; pf.y = pr.y - hy;
        pf.z = pr.x + hx; pf.w = pr.y + hy;
    } else {
        pf.x = -1.0f; pf.y = -1.0f; pf.z = -1.0f; pf.w = -1.0f;  // degenerate: inter=0
    }
    float pa = (pf.z - pf.x) * (pf.w - pf.y);

    float bi = -1.0f, bd = 1.0f; int bg = 0;
    for (int g = 0; g < gnum; g++) {
        float in_ = inter_fn(str[g], pf);
        float dn_ = sa[g] + pa - in_;
        unsigned k32 = __float_as_uint(__fdividef(in_, dn_));
        if (in_ * bd > bi * dn_) { bi = in_; bd = dn_; bg = g; }
        unsigned mx = __reduce_max_sync(0xFFFFFFFFu, k32);
        unsigned bal = __ballot_sync(0xFFFFFFFFu, k32 == mx);
        if (lane == __ffs(bal) - 1)
            swk[g][wid] = ((unsigned long long)mx << 32) | (0xFFFFFFFFu - (unsigned)p);
    }
    __syncthreads();
    if (tid < Gn && tid < gnum) {
        unsigned long long best = swk[tid][0];
        #pragma unroll
        for (int w2 = 1; w2 < 8; w2++) {
            unsigned long long o = swk[tid][w2];
            if (o > best) best = o;
        }
        d_gpart[((size_t)b * Gn + tid) * NB3 + chunk] = best;
    }
    if (p < Pn) {
        float2 r; r.x = bi / bd; r.y = __int_as_float(bg);   // exact IEEE ov
        d_povg[(size_t)b * Pn + p] = r;
    }
}

// ---------------- KB: reduce per-g partials, emit fix-up tables ----------------
__global__ void k_B(const int* __restrict__ gnum_arr) {
    int idx = blockIdx.x * NTH + threadIdx.x;
    if (idx >= Bn * Gn) return;
    int b = idx / Gn, g = idx % Gn;
    if (g >= min(gnum_arr[b], Gn)) return;
    const unsigned long long* row = &d_gpart[(size_t)idx * NB3];
    unsigned long long best = row[0];
    for (int k = 1; k < NB3; k++) {
        unsigned long long v = row[k];
        if (v > best) best = v;
    }
    unsigned p = 0xFFFFFFFFu - (unsigned)best;
    d_bpi[idx] = p;
    atomicOr(&d_cmask[b * NB3 + (p / NTH)], 1ull << g);
    if ((unsigned)(best >> 32) >= 0x3E4CCCCDu) {          // iou >= 0.2f
        atomicOr(&d_vmask[b], 1ull << g);
        atomicOr(&d_hv[b], 1);
    }
}

// ---------------- KC: losses + ce (full-grid; no IoU work) ----------------
__global__ void k_C(const float* __restrict__ loc, const float* __restrict__ conf,
                    const float* __restrict__ lmd, const float* __restrict__ priors,
                    const float* __restrict__ gtb, const int* __restrict__ gtl,
                    const float* __restrict__ gtlm, const int* __restrict__ img) {
    __shared__ float4 str[Gn];
    __shared__ float  slm[Gn * 10];
    __shared__ int    slab[Gn];
    __shared__ unsigned sbpi[Gn];
    __shared__ float  wll[8], wlm[8], wpce[8];
    __shared__ int    wnp[8];
    int b = blockIdx.y, tid = threadIdx.x;
    int lane = tid & 31, wid = tid >> 5;
    float w = (float)img[b * 2 + 1];
    float h = (float)img[b * 2 + 0];
    if (tid < Gn * 4)
        ((float*)str)[tid] = gtb[b * Gn * 4 + tid] / ((tid & 1) ? h : w);
    if (tid < Gn * 10 - NTH)
        slm[tid + NTH] = gtlm[b * Gn * 10 + tid + NTH] / (((tid + NTH) & 1) ? h : w);
    slm[tid] = gtlm[b * Gn * 10 + tid] / ((tid & 1) ? h : w);
    if (tid < Gn) {
        int lab = gtl[b * Gn + tid];
        if (lab == 0) lab = 1;
        if (gtlm[b * Gn * 10 + tid * 10] < 0.0f) lab = -1;   // sign preserved by /w
        slab[tid] = lab;
        sbpi[tid] = d_bpi[b * Gn + tid];
    }
    __syncthreads();
    int hv = d_hv[b];
    unsigned long long vm = d_vmask[b];
    unsigned long long cm_all = d_cmask[b * NB3 + blockIdx.x];

    int p = blockIdx.x * NTH + tid;
    float ll = 0.0f, llm = 0.0f, pce = 0.0f;
    int npk = 0;
    if (p < Pn) {
        long long base = (long long)b * Pn + p;
        float2 og = d_povg[base];
        float ov = og.x;
        int bg = __float_as_int(og.y);
        unsigned long long cm = cm_all;
        while (cm) {
            int j = __ffsll((long long)cm) - 1;   // ascending j => later j wins
            cm &= cm - 1;
            if (sbpi[j] == (unsigned)p) {
                bg = j;
                if ((vm >> j) & 1ull) ov = 2.0f;
            }
        }
        int lab = slab[bg];
        int c = (hv && ov >= 0.35f) ? lab : 0;
        bool pos = (c != 0), pos1 = (c > 0);
        float2 cd = ((const float2*)conf)[base];
        float m = fmaxf(cd.x, cd.y);
        float logz = m + logf(expf(cd.x - m) + expf(cd.y - m));
        float ce = logz - (pos ? cd.y : cd.x);
        d_ce[base] = pos ? -1.0f : ce;
        if (pos) {
            npk = 1; pce = ce;
            float4 pr = ((const float4*)priors)[p];
            float4 t = str[bg];
            float s0 = 0.1f * pr.z, s1 = 0.1f * pr.w;
            float tx = ((t.x + t.z) * 0.5f - pr.x) / s0;
            float ty = ((t.y + t.w) * 0.5f - pr.y) / s1;
            float tw = logf((t.z - t.x) / pr.z) / 0.2f;
            float th = logf((t.w - t.y) / pr.w) / 0.2f;
            float4 lc = ((const float4*)loc)[base];
            ll = sl1(lc.x - tx) + sl1(lc.y - ty) + sl1(lc.z - tw) + sl1(lc.w - th);
            if (pos1) {
                npk |= (1 << 16);
                const float2* lrow = (const float2*)(lmd + base * 10);
                const float* tg = &slm[bg * 10];
                #pragma unroll
                for (int i = 0; i < 5; i++) {
                    float2 lv = lrow[i];
                    float ttx = (tg[2*i]   - pr.x) / s0;
                    float tty = (tg[2*i+1] - pr.y) / s1;
                    llm += sl1(lv.x - ttx) + sl1(lv.y - tty);
                }
            }
        }
    }
    #pragma unroll
    for (int off = 16; off > 0; off >>= 1) {
        ll  += __shfl_down_sync(0xFFFFFFFFu, ll,  off);
        llm += __shfl_down_sync(0xFFFFFFFFu, llm, off);
        pce += __shfl_down_sync(0xFFFFFFFFu, pce, off);
        npk += __shfl_down_sync(0xFFFFFFFFu, npk, off);
    }
    if (lane == 0) { wll[wid] = ll; wlm[wid] = llm; wpce[wid] = pce; wnp[wid] = npk; }
    __syncthreads();
    if (tid == 0) {
        float a = 0, c = 0, d = 0; int e = 0;
        #pragma unroll
        for (int i = 0; i < 8; i++) { a += wll[i]; c += wlm[i]; d += wpce[i]; e += wnp[i]; }
        int idx = b * NB3 + blockIdx.x;
        d_part_ll[idx] = a; d_part_lm[idx] = c; d_part_pce[idx] = d; d_part_np[idx] = e;
    }
}

// ---------------- K5: per-batch reduce + radix select, ce in registers ------------
// Per-warp PRIVATE histograms (no smem atomics): hist[32][256].
__global__ void __launch_bounds__(NTHB, 1) k_batch() {
    int b = blockIdx.x, tid = threadIdx.x;
    int lane = tid & 31, wid = tid >> 5;
    __shared__ int    hist[32][256];   // 32 KB: one row per warp
    __shared__ int    sred[256];
    __shared__ double sdw[32];
    __shared__ int    siw[32];
    __shared__ unsigned s_prefix;
    __shared__ int s_rem;
    __shared__ double s_ll, s_lm, s_pce;
    __shared__ int s_np, s_np1;

    double vll = 0, vlm = 0, vpce = 0; int vnp = 0;
    if (tid < NB3) {
        int idx = b * NB3 + tid;
        vll = (double)d_part_ll[idx];
        vlm = (double)d_part_lm[idx];
        vpce = (double)d_part_pce[idx];
        vnp = d_part_np[idx];
    }
    #pragma unroll
    for (int off = 16; off > 0; off >>= 1) {
        vll  += __shfl_down_sync(0xFFFFFFFFu, vll,  off);
        vlm  += __shfl_down_sync(0xFFFFFFFFu, vlm,  off);
        vpce += __shfl_down_sync(0xFFFFFFFFu, vpce, off);
        vnp  += __shfl_down_sync(0xFFFFFFFFu, vnp,  off);
    }
    if (lane == 0) { sdw[wid] = vll; siw[wid] = vnp; }
    __syncthreads();
    if (tid == 0) {
        double a = 0; int e = 0;
        for (int i = 0; i < 32; i++) { a += sdw[i]; e += siw[i]; }
        s_ll = a;
        s_np = e & 0xFFFF; s_np1 = e >> 16;
    }
    __syncthreads();
    if (lane == 0) sdw[wid] = vlm;
    __syncthreads();
    if (tid == 0) { double a = 0; for (int i = 0; i < 32; i++) a += sdw[i]; s_lm = a; }
    __syncthreads();
    if (lane == 0) sdw[wid] = vpce;
    __syncthreads();
    if (tid == 0) { double a = 0; for (int i = 0; i < 32; i++) a += sdw[i]; s_pce = a; }
    // clear all private histograms
    #pragma unroll
    for (int i = 0; i < 8; i++) ((int*)hist)[tid + i * NTHB] = 0;
    __syncthreads();

    // read ce ONCE into registers; reuse across all radix passes
    float ce_r[KPT];
    long long base = (long long)b * Pn;
    #pragma unroll
    for (int k = 0; k < KPT; k++) {
        int p = tid + k * NTHB;
        ce_r[k] = (p < Pn) ? d_ce[base + p] : -1.0f;
    }

    int np = s_np;
    int K = min(7 * np, Pn - 1);
    int cntnon = Pn - np;
    double negsum = 0.0;

    if (K > 0) {
        if (K >= cntnon) {
            double locs = 0.0;
            #pragma unroll
            for (int k = 0; k < KPT; k++) if (ce_r[k] >= 0.0f) locs += (double)ce_r[k];
            #pragma unroll
            for (int off = 16; off > 0; off >>= 1) locs += __shfl_down_sync(0xFFFFFFFFu, locs, off);
            if (lane == 0) sdw[wid] = locs;
            __syncthreads();
            if (tid == 0) { double a = 0; for (int i = 0; i < 32; i++) a += sdw[i]; negsum = a; }
        } else {
            if (tid == 0) { s_prefix = 0u; s_rem = K; }
            __syncthreads();
            for (int shift = 24; shift >= 0; shift -= 8) {
                unsigned mask = (shift == 24) ? 0u : (0xFFFFFFFFu << (shift + 8));
                unsigned pref = s_prefix;
                // fixed trip count; OOB/pos = -1 sentinel (warp-uniform collectives).
                // Leader per distinct bin does a PLAIN RMW on this warp's private row:
                // distinct leaders => distinct addresses => no race, no atomics.
                #pragma unroll
                for (int k = 0; k < KPT; k++) {
                    float v = ce_r[k];
                    bool valid = false; unsigned bin = 0xFFFFFFFFu;
                    if (v >= 0.0f) {
                        unsigned u = __float_as_uint(v);
                        if ((u & mask) == pref) { valid = true; bin = (u >> shift) & 255u; }
                    }
                    unsigned mm = __match_any_sync(0xFFFFFFFFu, valid ? bin : 0xFFFFFFFFu);
                    if (valid && lane == (__ffs(mm) - 1))
                        hist[wid][bin] += __popc(mm);
                }
                __syncthreads();
                // column-sum the 32 private rows (coalesced per-w iteration)
                if (tid < 256) {
                    int s = 0;
                    #pragma unroll
                    for (int w = 0; w < 32; w++) s += hist[w][tid];
                    sred[tid] = s;
                }
                __syncthreads();
                if (tid == 0) {
                    int rem = s_rem, cum = 0, chosen = 0;
                    for (int v = 255; v >= 0; v--) {
                        int c = sred[v];
                        if (cum + c >= rem) { chosen = v; s_rem = rem - cum; break; }
                        cum += c;
                    }
                    s_prefix = pref | ((unsigned)chosen << shift);
                }
                __syncthreads();
                #pragma unroll
                for (int i = 0; i < 8; i++) ((int*)hist)[tid + i * NTHB] = 0;
                __syncthreads();
            }
            unsigned T = s_prefix;
            int rem = s_rem;
            double locs = 0.0;
            #pragma unroll
            for (int k = 0; k < KPT; k++) {
                float v = ce_r[k];
                if (v >= 0.0f && __float_as_uint(v) > T) locs += (double)v;
            }
            #pragma unroll
            for (int off = 16; off > 0; off >>= 1) locs += __shfl_down_sync(0xFFFFFFFFu, locs, off);
            if (lane == 0) sdw[wid] = locs;
            __syncthreads();
            if (tid == 0) {
                double a = 0; for (int i = 0; i < 32; i++) a += sdw[i];
                negsum = a + (double)rem * (double)__uint_as_float(T);
            }
        }
    }
    if (tid == 0) {
        d_b_ll[b] = s_ll;
        d_b_lm[b] = s_lm;
        d_b_lc[b] = s_pce + negsum;
        d_b_np[b] = np;
        d_b_np1[b] = s_np1;
    }
}

// ---------------- K6: final combine ----------------
__global__ void k_final(float* __restrict__ out) {
    __shared__ double s1[Bn], s2[Bn], s3[Bn];
    __shared__ int i1[Bn], i2[Bn];
    int t = threadIdx.x;
    s1[t] = d_b_ll[t]; s2[t] = d_b_lc[t]; s3[t] = d_b_lm[t];
    i1[t] = d_b_np[t]; i2[t] = d_b_np1[t];
    __syncthreads();
    for (int s = Bn/2; s > 0; s >>= 1) {
        if (t < s) {
            s1[t] += s1[t+s]; s2[t] += s2[t+s]; s3[t] += s3[t+s];
            i1[t] += i1[t+s]; i2[t] += i2[t+s];
        }
        __syncthreads();
    }
    if (t == 0) {
        double N  = (double)(i1[0] > 0 ? i1[0] : 1);
        double N1 = (double)(i2[0] > 0 ? i2[0] : 1);
        out[0] = (float)(s1[0] / N);
        out[1] = (float)(s2[0] / N);
        out[2] = (float)(s3[0] / N1);
    }
}

// ---------------- launcher ----------------
extern "C" void kernel_launch(void* const* d_in, const int* in_sizes, int n_in,
                              void* d_out, int out_size) {
    const float* loc    = (const float*)d_in[0];
    const float* conf   = (const float*)d_in[1];
    const float* lmd    = (const float*)d_in[2];
    const float* priors = (const float*)d_in[3];
    const float* gtb    = (const float*)d_in[4];
    const int*   gtl    = (const int*)d_in[5];
    const float* gtlm   = (const float*)d_in[6];
    const int*   gnum   = (const int*)d_in[7];
    const int*   img    = (const int*)d_in[8];
    float* out = (float*)d_out;

    k_A<<<dim3(NB3, Bn), NTH>>>(gnum, priors, gtb, img);
    k_B<<<(Bn * Gn + NTH - 1) / NTH, NTH>>>(gnum);
    k_C<<<dim3(NB3, Bn), NTH>>>(loc, conf, lmd, priors, gtb, gtl, gtlm, img);
    k_batch<<<Bn, NTHB>>>();
    k_final<<<1, Bn>>>(out);
}

// round 16
// speedup vs baseline: 1.0884x; 1.0884x over previous
#include <cuda_runtime.h>
#include <math.h>
#include <stdint.h>

#define Bn 64
#define Pn 25200
#define Gn 48
#define NB3 99            // ceil(Pn/256)
#define NTH 256
#define NTHB 1024         // k_batch threads
#define KPT 25            // ce values per thread in k_batch (25*1024 >= 25200)

// ---------------- scratch (no allocations allowed) ----------------
__device__ unsigned long long d_gpart[Bn*Gn*NB3]; // per-(b,g,chunk) partial argmax keys
__device__ unsigned d_bpi[Bn*Gn];            // best prior index per gt
__device__ unsigned long long d_vmask[Bn];   // valid-gt bitmask per batch
__device__ unsigned long long d_cmask[Bn*NB3]; // per-(batch,chunk) gt-index mask
__device__ float2 d_povg[Bn*Pn];             // per-prior (exact ov, bg as int bits)
__device__ float  d_ce[Bn*Pn];               // ce for non-pos, -1 for pos
__device__ int    d_hv[Bn];                  // has_valid per batch
__device__ float  d_part_ll[Bn*NB3];
__device__ float  d_part_lm[Bn*NB3];
__device__ float  d_part_pce[Bn*NB3];
__device__ int    d_part_np[Bn*NB3];         // np | (np1<<16)
__device__ double d_b_ll[Bn], d_b_lm[Bn], d_b_lc[Bn];
__device__ int    d_b_np[Bn], d_b_np1[Bn];

// ---------------- helpers ----------------
__device__ __forceinline__ float sl1(float d) {
    d = fabsf(d);
    return d < 1.0f ? 0.5f * d * d : d - 0.5f;
}

__device__ __forceinline__ float inter_fn(float4 t, float4 pf) {
    float ltx = fmaxf(t.x, pf.x), lty = fmaxf(t.y, pf.y);
    float rbx = fminf(t.z, pf.z), rby = fminf(t.w, pf.w);
    float iw = fmaxf(rbx - ltx, 0.0f), ih = fmaxf(rby - lty, 0.0f);
    return iw * ih;
}

// ---------------- KA: single-pass IoU, dual argmax (no prep kernel) --------------
__global__ void k_A(const int* __restrict__ gnum_arr, const float* __restrict__ priors,
                    const float* __restrict__ gtb, const int* __restrict__ img) {
    __shared__ float4 str[Gn];
    __shared__ float  sa[Gn];
    __shared__ unsigned long long swk[Gn][8];
    int b = blockIdx.y, chunk = blockIdx.x;
    int tid = threadIdx.x, lane = tid & 31, wid = tid >> 5;

    float w = (float)img[b * 2 + 1];
    float h = (float)img[b * 2 + 0];
    if (tid < Gn * 4)
        ((float*)str)[tid] = gtb[b * Gn * 4 + tid] / ((tid & 1) ? h : w);
    if (tid < Gn) {
        float x1 = gtb[b*Gn*4 + tid*4+0] / w, y1 = gtb[b*Gn*4 + tid*4+1] / h;
        float x2 = gtb[b*Gn*4 + tid*4+2] / w, y2 = gtb[b*Gn*4 + tid*4+3] / h;
        sa[tid] = (x2 - x1) * (y2 - y1);
    }
    if (tid == 0) {
        d_cmask[b * NB3 + chunk] = 0ull;          // zeroed before B's atomicOr
        if (chunk == 0) { d_vmask[b] = 0ull; d_hv[b] = 0; }
    }
    __syncthreads();

    int gnum = min(gnum_arr[b], Gn);
    int p = chunk * NTH + tid;
    float4 pf;
    if (p < Pn) {
        float4 pr = ((const float4*)priors)[p];
        float hx = pr.z * 0.5f, hy = pr.w * 0.5f;
        pf.x = pr.x - hx; pf.y = pr.y - hy;
        pf.z = pr.x + hx; pf.w = pr.y + hy;
    } else {
        pf.x = -1.0f; pf.y = -1.0f; pf.z = -1.0f; pf.w = -1.0f;  // degenerate: inter=0
    }
    float pa = (pf.z - pf.x) * (pf.w - pf.y);

    float bi = -1.0f, bd = 1.0f; int bg = 0;
    for (int g = 0; g < gnum; g++) {
        float in_ = inter_fn(str[g], pf);
        float dn_ = sa[g] + pa - in_;
        unsigned k32 = __float_as_uint(__fdividef(in_, dn_));
        if (in_ * bd > bi * dn_) { bi = in_; bd = dn_; bg = g; }
        unsigned mx = __reduce_max_sync(0xFFFFFFFFu, k32);
        unsigned bal = __ballot_sync(0xFFFFFFFFu, k32 == mx);
        if (lane == __ffs(bal) - 1)
            swk[g][wid] = ((unsigned long long)mx << 32) | (0xFFFFFFFFu - (unsigned)p);
    }
    __syncthreads();
    if (tid < Gn && tid < gnum) {
        unsigned long long best = swk[tid][0];
        #pragma unroll
        for (int w2 = 1; w2 < 8; w2++) {
            unsigned long long o = swk[tid][w2];
            if (o > best) best = o;
        }
        d_gpart[((size_t)b * Gn + tid) * NB3 + chunk] = best;
    }
    if (p < Pn) {
        float2 r; r.x = bi / bd; r.y = __int_as_float(bg);   // exact IEEE ov
        d_povg[(size_t)b * Pn + p] = r;
    }
}

// ---------------- KB: reduce per-g partials, emit fix-up tables ----------------
__global__ void k_B(const int* __restrict__ gnum_arr) {
    int idx = blockIdx.x * NTH + threadIdx.x;
    if (idx >= Bn * Gn) return;
    int b = idx / Gn, g = idx % Gn;
    if (g >= min(gnum_arr[b], Gn)) return;
    const unsigned long long* row = &d_gpart[(size_t)idx * NB3];
    unsigned long long best = row[0];
    for (int k = 1; k < NB3; k++) {
        unsigned long long v = row[k];
        if (v > best) best = v;
    }
    unsigned p = 0xFFFFFFFFu - (unsigned)best;
    d_bpi[idx] = p;
    atomicOr(&d_cmask[b * NB3 + (p / NTH)], 1ull << g);
    if ((unsigned)(best >> 32) >= 0x3E4CCCCDu) {          // iou >= 0.2f
        atomicOr(&d_vmask[b], 1ull << g);
        atomicOr(&d_hv[b], 1);
    }
}

// ---------------- KC: losses + ce (full-grid; no IoU work) ----------------
__global__ void k_C(const float* __restrict__ loc, const float* __restrict__ conf,
                    const float* __restrict__ lmd, const float* __restrict__ priors,
                    const float* __restrict__ gtb, const int* __restrict__ gtl,
                    const float* __restrict__ gtlm, const int* __restrict__ img) {
    __shared__ float4 str[Gn];
    __shared__ float  slm[Gn * 10];
    __shared__ int    slab[Gn];
    __shared__ unsigned sbpi[Gn];
    __shared__ float  wll[8], wlm[8], wpce[8];
    __shared__ int    wnp[8];
    int b = blockIdx.y, tid = threadIdx.x;
    int lane = tid & 31, wid = tid >> 5;
    float w = (float)img[b * 2 + 1];
    float h = (float)img[b * 2 + 0];
    if (tid < Gn * 4)
        ((float*)str)[tid] = gtb[b * Gn * 4 + tid] / ((tid & 1) ? h : w);
    if (tid < Gn * 10 - NTH)
        slm[tid + NTH] = gtlm[b * Gn * 10 + tid + NTH] / (((tid + NTH) & 1) ? h : w);
    slm[tid] = gtlm[b * Gn * 10 + tid] / ((tid & 1) ? h : w);
    if (tid < Gn) {
        int lab = gtl[b * Gn + tid];
        if (lab == 0) lab = 1;
        if (gtlm[b * Gn * 10 + tid * 10] < 0.0f) lab = -1;   // sign preserved by /w
        slab[tid] = lab;
        sbpi[tid] = d_bpi[b * Gn + tid];
    }
    __syncthreads();
    int hv = d_hv[b];
    unsigned long long vm = d_vmask[b];
    unsigned long long cm_all = d_cmask[b * NB3 + blockIdx.x];

    int p = blockIdx.x * NTH + tid;
    float ll = 0.0f, llm = 0.0f, pce = 0.0f;
    int npk = 0;
    if (p < Pn) {
        long long base = (long long)b * Pn + p;
        float2 og = d_povg[base];
        float ov = og.x;
        int bg = __float_as_int(og.y);
        unsigned long long cm = cm_all;
        while (cm) {
            int j = __ffsll((long long)cm) - 1;   // ascending j => later j wins
            cm &= cm - 1;
            if (sbpi[j] == (unsigned)p) {
                bg = j;
                if ((vm >> j) & 1ull) ov = 2.0f;
            }
        }
        int lab = slab[bg];
        int c = (hv && ov >= 0.35f) ? lab : 0;
        bool pos = (c != 0), pos1 = (c > 0);
        float2 cd = ((const float2*)conf)[base];
        float m = fmaxf(cd.x, cd.y);
        float logz = m + logf(expf(cd.x - m) + expf(cd.y - m));
        float ce = logz - (pos ? cd.y : cd.x);
        d_ce[base] = pos ? -1.0f : ce;
        if (pos) {
            npk = 1; pce = ce;
            float4 pr = ((const float4*)priors)[p];
            float4 t = str[bg];
            float s0 = 0.1f * pr.z, s1 = 0.1f * pr.w;
            float tx = ((t.x + t.z) * 0.5f - pr.x) / s0;
            float ty = ((t.y + t.w) * 0.5f - pr.y) / s1;
            float tw = logf((t.z - t.x) / pr.z) / 0.2f;
            float th = logf((t.w - t.y) / pr.w) / 0.2f;
            float4 lc = ((const float4*)loc)[base];
            ll = sl1(lc.x - tx) + sl1(lc.y - ty) + sl1(lc.z - tw) + sl1(lc.w - th);
            if (pos1) {
                npk |= (1 << 16);
                const float2* lrow = (const float2*)(lmd + base * 10);
                const float* tg = &slm[bg * 10];
                #pragma unroll
                for (int i = 0; i < 5; i++) {
                    float2 lv = lrow[i];
                    float ttx = (tg[2*i]   - pr.x) / s0;
                    float tty = (tg[2*i+1] - pr.y) / s1;
                    llm += sl1(lv.x - ttx) + sl1(lv.y - tty);
                }
            }
        }
    }
    #pragma unroll
    for (int off = 16; off > 0; off >>= 1) {
        ll  += __shfl_down_sync(0xFFFFFFFFu, ll,  off);
        llm += __shfl_down_sync(0xFFFFFFFFu, llm, off);
        pce += __shfl_down_sync(0xFFFFFFFFu, pce, off);
        npk += __shfl_down_sync(0xFFFFFFFFu, npk, off);
    }
    if (lane == 0) { wll[wid] = ll; wlm[wid] = llm; wpce[wid] = pce; wnp[wid] = npk; }
    __syncthreads();
    if (tid == 0) {
        float a = 0, c = 0, d = 0; int e = 0;
        #pragma unroll
        for (int i = 0; i < 8; i++) { a += wll[i]; c += wlm[i]; d += wpce[i]; e += wnp[i]; }
        int idx = b * NB3 + blockIdx.x;
        d_part_ll[idx] = a; d_part_lm[idx] = c; d_part_pce[idx] = d; d_part_np[idx] = e;
    }
}

// ---------------- K5: per-batch reduce + radix select -----------------------------
// ce in registers; parallel suffix-scan crossover (R15 scan bug fixed: out-of-range
// shfl_down returns caller's own value, so accumulate is predicated on lane+d<32).
__global__ void __launch_bounds__(NTHB, 1) k_batch() {
    int b = blockIdx.x, tid = threadIdx.x;
    int lane = tid & 31, wid = tid >> 5;
    __shared__ int    hist[256];
    __shared__ int    warpTot[8];
    __shared__ double sd1[32], sd2[32], sd3[32];
    __shared__ int    siw[32];
    __shared__ unsigned s_prefix;
    __shared__ int s_rem;
    __shared__ double s_ll, s_lm, s_pce;
    __shared__ int s_np, s_np1;

    // ---- combine k_C partials: one barrier, warp0 second-level reduce ----
    double vll = 0, vlm = 0, vpce = 0; int vnp = 0;
    if (tid < NB3) {
        int idx = b * NB3 + tid;
        vll = (double)d_part_ll[idx];
        vlm = (double)d_part_lm[idx];
        vpce = (double)d_part_pce[idx];
        vnp = d_part_np[idx];
    }
    #pragma unroll
    for (int off = 16; off > 0; off >>= 1) {
        vll  += __shfl_down_sync(0xFFFFFFFFu, vll,  off);
        vlm  += __shfl_down_sync(0xFFFFFFFFu, vlm,  off);
        vpce += __shfl_down_sync(0xFFFFFFFFu, vpce, off);
        vnp  += __shfl_down_sync(0xFFFFFFFFu, vnp,  off);
    }
    if (lane == 0) { sd1[wid] = vll; sd2[wid] = vlm; sd3[wid] = vpce; siw[wid] = vnp; }
    if (tid < 256) hist[tid] = 0;
    __syncthreads();
    if (wid == 0) {
        double a = sd1[lane], c = sd2[lane], d = sd3[lane]; int e = siw[lane];
        #pragma unroll
        for (int off = 16; off > 0; off >>= 1) {
            a += __shfl_down_sync(0xFFFFFFFFu, a, off);
            c += __shfl_down_sync(0xFFFFFFFFu, c, off);
            d += __shfl_down_sync(0xFFFFFFFFu, d, off);
            e += __shfl_down_sync(0xFFFFFFFFu, e, off);
        }
        if (lane == 0) {
            s_ll = a; s_lm = c; s_pce = d;
            s_np = e & 0xFFFF; s_np1 = e >> 16;
            s_prefix = 0u;
        }
    }
    __syncthreads();

    // ---- read ce ONCE into registers ----
    float ce_r[KPT];
    long long base = (long long)b * Pn;
    #pragma unroll
    for (int k = 0; k < KPT; k++) {
        int p = tid + k * NTHB;
        ce_r[k] = (p < Pn) ? d_ce[base + p] : -1.0f;
    }

    int np = s_np;
    int K = min(7 * np, Pn - 1);
    int cntnon = Pn - np;
    double negsum = 0.0;   // meaningful at tid 0 only

    if (K > 0 && K >= cntnon) {
        // sum ALL candidates
        double locs = 0.0;
        #pragma unroll
        for (int k = 0; k < KPT; k++) if (ce_r[k] >= 0.0f) locs += (double)ce_r[k];
        #pragma unroll
        for (int off = 16; off > 0; off >>= 1) locs += __shfl_down_sync(0xFFFFFFFFu, locs, off);
        if (lane == 0) sd1[wid] = locs;
        __syncthreads();
        if (wid == 0) {
            double a = sd1[lane];
            #pragma unroll
            for (int off = 16; off > 0; off >>= 1) a += __shfl_down_sync(0xFFFFFFFFu, a, off);
            if (lane == 0) negsum = a;
        }
    } else if (K > 0) {
        if (tid == 0) s_rem = K;
        __syncthreads();
        for (int shift = 24; shift >= 0; shift -= 8) {
            unsigned mask = (shift == 24) ? 0u : (0xFFFFFFFFu << (shift + 8));
            unsigned pref = s_prefix;          // read before any write this pass
            int remLocal = s_rem;
            // histogram (fixed trip count; -1 sentinel keeps collectives warp-uniform)
            #pragma unroll
            for (int k = 0; k < KPT; k++) {
                float v = ce_r[k];
                bool valid = false; unsigned bin = 0xFFFFFFFFu;
                if (v >= 0.0f) {
                    unsigned u = __float_as_uint(v);
                    if ((u & mask) == pref) { valid = true; bin = (u >> shift) & 255u; }
                }
                unsigned mm = __match_any_sync(0xFFFFFFFFu, valid ? bin : 0xFFFFFFFFu);
                if (valid && lane == (__ffs(mm) - 1))
                    atomicAdd(&hist[bin], __popc(mm));
            }
            __syncthreads();
            // parallel crossover: 8 full warps, one bin per thread.
            // CORRECT inclusive suffix sum: all lanes shuffle (warp-uniform),
            // accumulate only when source lane is in range.
            int cnt = 0, sfx = 0;
            if (tid < 256) {
                cnt = hist[tid];
                hist[tid] = 0;                 // fused clear (only tid<256 touch hist)
                sfx = cnt;
                #pragma unroll
                for (int d = 1; d < 32; d <<= 1) {
                    int o = __shfl_down_sync(0xFFFFFFFFu, sfx, d);
                    if (lane + d < 32) sfx += o;
                }
                if (lane == 0) warpTot[wid] = sfx;
            }
            __syncthreads();
            if (tid < 256) {
                int H = 0;
                #pragma unroll
                for (int w2 = 0; w2 < 8; w2++) if (w2 > wid) H += warpTot[w2];
                int Sx = sfx - cnt + H;        // S_excl = strictly-higher-bin count
                if (Sx < remLocal && Sx + cnt >= remLocal) {   // unique bin
                    s_prefix = pref | ((unsigned)tid << shift);
                    s_rem = remLocal - Sx;
                }
            }
            __syncthreads();
        }
        unsigned T = s_prefix;
        int rem = s_rem;
        double locs = 0.0;
        #pragma unroll
        for (int k = 0; k < KPT; k++) {
            float v = ce_r[k];
            if (v >= 0.0f && __float_as_uint(v) > T) locs += (double)v;
        }
        #pragma unroll
        for (int off = 16; off > 0; off >>= 1) locs += __shfl_down_sync(0xFFFFFFFFu, locs, off);
        if (lane == 0) sd1[wid] = locs;
        __syncthreads();
        if (wid == 0) {
            double a = sd1[lane];
            #pragma unroll
            for (int off = 16; off > 0; off >>= 1) a += __shfl_down_sync(0xFFFFFFFFu, a, off);
            if (lane == 0) negsum = a + (double)rem * (double)__uint_as_float(T);
        }
    }
    if (tid == 0) {
        d_b_ll[b] = s_ll;
        d_b_lm[b] = s_lm;
        d_b_lc[b] = s_pce + negsum;
        d_b_np[b] = np;
        d_b_np1[b] = s_np1;
    }
}

// ---------------- K6: final combine ----------------
__global__ void k_final(float* __restrict__ out) {
    __shared__ double s1[Bn], s2[Bn], s3[Bn];
    __shared__ int i1[Bn], i2[Bn];
    int t = threadIdx.x;
    s1[t] = d_b_ll[t]; s2[t] = d_b_lc[t]; s3[t] = d_b_lm[t];
    i1[t] = d_b_np[t]; i2[t] = d_b_np1[t];
    __syncthreads();
    for (int s = Bn/2; s > 0; s >>= 1) {
        if (t < s) {
            s1[t] += s1[t+s]; s2[t] += s2[t+s]; s3[t] += s3[t+s];
            i1[t] += i1[t+s]; i2[t] += i2[t+s];
        }
        __syncthreads();
    }
    if (t == 0) {
        double N  = (double)(i1[0] > 0 ? i1[0] : 1);
        double N1 = (double)(i2[0] > 0 ? i2[0] : 1);
        out[0] = (float)(s1[0] / N);
        out[1] = (float)(s2[0] / N);
        out[2] = (float)(s3[0] / N1);
    }
}

// ---------------- launcher ----------------
extern "C" void kernel_launch(void* const* d_in, const int* in_sizes, int n_in,
                              void* d_out, int out_size) {
    const float* loc    = (const float*)d_in[0];
    const float* conf   = (const float*)d_in[1];
    const float* lmd    = (const float*)d_in[2];
    const float* priors = (const float*)d_in[3];
    const float* gtb    = (const float*)d_in[4];
    const int*   gtl    = (const int*)d_in[5];
    const float* gtlm   = (const float*)d_in[6];
    const int*   gnum   = (const int*)d_in[7];
    const int*   img    = (const int*)d_in[8];
    float* out = (float*)d_out;

    k_A<<<dim3(NB3, Bn), NTH>>>(gnum, priors, gtb, img);
    k_B<<<(Bn * Gn + NTH - 1) / NTH, NTH>>>(gnum);
    k_C<<<dim3(NB3, Bn), NTH>>>(loc, conf, lmd, priors, gtb, gtl, gtlm, img);
    k_batch<<<Bn, NTHB>>>();
    k_final<<<1, Bn>>>(out);
}

// round 17
// speedup vs baseline: 1.1304x; 1.0386x over previous
#include <cuda_runtime.h>
#include <math.h>
#include <stdint.h>

#define Bn 64
#define Pn 25200
#define Gn 48
#define NB3 99            // ceil(Pn/256)
#define NTH 256
#define NTHB 1024         // k_batch2 threads
#define KPT 25            // ce values per thread in k_batch2 (25*1024 >= 25200)

// ---------------- scratch (no allocations allowed) ----------------
__device__ unsigned long long d_gpart[Bn*Gn*NB3]; // per-(b,g,chunk) partial argmax keys
__device__ float  d_ce[Bn*Pn];               // ce for non-pos, -1 for pos
__device__ float  d_part_ll[Bn*NB3];
__device__ float  d_part_lm[Bn*NB3];
__device__ float  d_part_pce[Bn*NB3];
__device__ int    d_part_np[Bn*NB3];         // np | (np1<<16)
__device__ double d_b_ll[Bn], d_b_lm[Bn], d_b_lc[Bn];
__device__ int    d_b_np[Bn], d_b_np1[Bn];

// ---------------- helpers ----------------
__device__ __forceinline__ float sl1(float d) {
    d = fabsf(d);
    return d < 1.0f ? 0.5f * d * d : d - 0.5f;
}

__device__ __forceinline__ float inter_fn(float4 t, float4 pf) {
    float ltx = fmaxf(t.x, pf.x), lty = fmaxf(t.y, pf.y);
    float rbx = fminf(t.z, pf.z), rby = fminf(t.w, pf.w);
    float iw = fmaxf(rbx - ltx, 0.0f), ih = fmaxf(rby - lty, 0.0f);
    return iw * ih;
}

// Per-prior loss contribution (assumes hv=1). Shared by k_A epilogue and the
// correction step in k_batch2 so old/new contributions use identical FP ops.
struct Contrib { float ll, llm, pce, ce; int np, np1; bool pos; };
__device__ __forceinline__ Contrib contrib_fn(
        int p, float ov, int bg,
        const float* __restrict__ loc_b, const float* __restrict__ conf_b,
        const float* __restrict__ lmd_b, const float* __restrict__ priors,
        const float4* str, const float* slm, const int* slab) {
    Contrib r; r.ll = 0.0f; r.llm = 0.0f; r.pce = 0.0f; r.np = 0; r.np1 = 0;
    int lab = slab[bg];
    int c = (ov >= 0.35f) ? lab : 0;
    bool pos = (c != 0), pos1 = (c > 0);
    float2 cd = ((const float2*)conf_b)[p];
    float m = fmaxf(cd.x, cd.y);
    float logz = m + logf(expf(cd.x - m) + expf(cd.y - m));
    float ce = logz - (pos ? cd.y : cd.x);
    r.ce = ce; r.pos = pos;
    if (pos) {
        r.np = 1; r.pce = ce;
        float4 pr = ((const float4*)priors)[p];
        float4 t = str[bg];
        float s0 = 0.1f * pr.z, s1 = 0.1f * pr.w;
        float tx = ((t.x + t.z) * 0.5f - pr.x) / s0;
        float ty = ((t.y + t.w) * 0.5f - pr.y) / s1;
        float tw = logf((t.z - t.x) / pr.z) / 0.2f;
        float th = logf((t.w - t.y) / pr.w) / 0.2f;
        float4 lc = ((const float4*)loc_b)[p];
        r.ll = sl1(lc.x - tx) + sl1(lc.y - ty) + sl1(lc.z - tw) + sl1(lc.w - th);
        if (pos1) {
            r.np1 = 1;
            const float2* lrow = (const float2*)(lmd_b + p * 10);
            const float* tg = &slm[bg * 10];
            #pragma unroll
            for (int i = 0; i < 5; i++) {
                float2 lv = lrow[i];
                float ttx = (tg[2*i]   - pr.x) / s0;
                float tty = (tg[2*i+1] - pr.y) / s1;
                r.llm += sl1(lv.x - ttx) + sl1(lv.y - tty);
            }
        }
    }
    return r;
}

// ---------------- KA: IoU dual argmax + uncorrected loss epilogue ----------------
__global__ void k_A(const int* __restrict__ gnum_arr, const float* __restrict__ priors,
                    const float* __restrict__ gtb, const int* __restrict__ gtl,
                    const float* __restrict__ gtlm, const int* __restrict__ img,
                    const float* __restrict__ loc, const float* __restrict__ conf,
                    const float* __restrict__ lmd) {
    __shared__ float4 str[Gn];
    __shared__ float  sa[Gn];
    __shared__ float  slm[Gn * 10];
    __shared__ int    slab[Gn];
    __shared__ unsigned long long swk[Gn][8];
    __shared__ float  wll[8], wlm[8], wpce[8];
    __shared__ int    wnp[8];
    int b = blockIdx.y, chunk = blockIdx.x;
    int tid = threadIdx.x, lane = tid & 31, wid = tid >> 5;

    float w = (float)img[b * 2 + 1];
    float h = (float)img[b * 2 + 0];
    if (tid < Gn * 4)
        ((float*)str)[tid] = gtb[b * Gn * 4 + tid] / ((tid & 1) ? h : w);
    if (tid < Gn) {
        float x1 = gtb[b*Gn*4 + tid*4+0] / w, y1 = gtb[b*Gn*4 + tid*4+1] / h;
        float x2 = gtb[b*Gn*4 + tid*4+2] / w, y2 = gtb[b*Gn*4 + tid*4+3] / h;
        sa[tid] = (x2 - x1) * (y2 - y1);
        int lab = gtl[b * Gn + tid];
        if (lab == 0) lab = 1;
        if (gtlm[b * Gn * 10 + tid * 10] < 0.0f) lab = -1;
        slab[tid] = lab;
    }
    if (tid < Gn * 10 - NTH)
        slm[tid + NTH] = gtlm[b * Gn * 10 + tid + NTH] / (((tid + NTH) & 1) ? h : w);
    slm[tid] = gtlm[b * Gn * 10 + tid] / ((tid & 1) ? h : w);
    __syncthreads();

    int gnum = min(gnum_arr[b], Gn);
    int p = chunk * NTH + tid;
    float4 pr; float4 pf;
    if (p < Pn) {
        pr = ((const float4*)priors)[p];
        float hx = pr.z * 0.5f, hy = pr.w * 0.5f;
        pf.x = pr.x - hx; pf.y = pr.y - hy;
        pf.z = pr.x + hx; pf.w = pr.y + hy;
    } else {
        pf.x = -1.0f; pf.y = -1.0f; pf.z = -1.0f; pf.w = -1.0f;  // degenerate: inter=0
    }
    float pa = (pf.z - pf.x) * (pf.w - pf.y);

    float bi = -1.0f, bd = 1.0f; int bg = 0;
    for (int g = 0; g < gnum; g++) {
        float in_ = inter_fn(str[g], pf);
        float dn_ = sa[g] + pa - in_;
        unsigned k32 = __float_as_uint(__fdividef(in_, dn_));
        if (in_ * bd > bi * dn_) { bi = in_; bd = dn_; bg = g; }
        unsigned mx = __reduce_max_sync(0xFFFFFFFFu, k32);
        unsigned bal = __ballot_sync(0xFFFFFFFFu, k32 == mx);
        if (lane == __ffs(bal) - 1)
            swk[g][wid] = ((unsigned long long)mx << 32) | (0xFFFFFFFFu - (unsigned)p);
    }
    __syncthreads();
    if (tid < Gn && tid < gnum) {
        unsigned long long best = swk[tid][0];
        #pragma unroll
        for (int w2 = 1; w2 < 8; w2++) {
            unsigned long long o = swk[tid][w2];
            if (o > best) best = o;
        }
        d_gpart[((size_t)b * Gn + tid) * NB3 + chunk] = best;
    }

    // ---- uncorrected loss epilogue (fix-ups applied later in k_batch2) ----
    long long baseP = (long long)b * Pn;
    const float* loc_b  = loc  + baseP * 4;
    const float* conf_b = conf + baseP * 2;
    const float* lmd_b  = lmd  + baseP * 10;
    float ll = 0.0f, llm = 0.0f, pce = 0.0f;
    int npk = 0;
    if (p < Pn) {
        float ov = bi / bd;                    // exact IEEE
        Contrib r = contrib_fn(p, ov, bg, loc_b, conf_b, lmd_b, priors, str, slm, slab);
        d_ce[baseP + p] = r.pos ? -1.0f : r.ce;
        ll = r.ll; llm = r.llm; pce = r.pce;
        npk = r.np | (r.np1 << 16);
    }
    #pragma unroll
    for (int off = 16; off > 0; off >>= 1) {
        ll  += __shfl_down_sync(0xFFFFFFFFu, ll,  off);
        llm += __shfl_down_sync(0xFFFFFFFFu, llm, off);
        pce += __shfl_down_sync(0xFFFFFFFFu, pce, off);
        npk += __shfl_down_sync(0xFFFFFFFFu, npk, off);
    }
    if (lane == 0) { wll[wid] = ll; wlm[wid] = llm; wpce[wid] = pce; wnp[wid] = npk; }
    __syncthreads();
    if (tid == 0) {
        float a = 0, c = 0, d = 0; int e = 0;
        #pragma unroll
        for (int i = 0; i < 8; i++) { a += wll[i]; c += wlm[i]; d += wpce[i]; e += wnp[i]; }
        int idx = b * NB3 + chunk;
        d_part_ll[idx] = a; d_part_lm[idx] = c; d_part_pce[idx] = d; d_part_np[idx] = e;
    }
}

// ---------------- K_batch2: gt-reduce + fix-up correction + combine + select ------
__global__ void __launch_bounds__(NTHB, 1) k_batch2(
        const int* __restrict__ gnum_arr, const float* __restrict__ priors,
        const float* __restrict__ gtb, const int* __restrict__ gtl,
        const float* __restrict__ gtlm, const int* __restrict__ img,
        const float* __restrict__ loc, const float* __restrict__ conf,
        const float* __restrict__ lmd) {
    int b = blockIdx.x, tid = threadIdx.x;
    int lane = tid & 31, wid = tid >> 5;
    __shared__ float4 str[Gn];
    __shared__ float  sa[Gn];
    __shared__ float  slm[Gn * 10];
    __shared__ int    slab[Gn];
    __shared__ unsigned sbpi[Gn];
    __shared__ int    svalid[Gn];
    __shared__ double sdll[Gn], sdlm[Gn], sdpce[Gn];
    __shared__ int    sdnp[Gn], sdnp1[Gn];
    __shared__ int    hist[256];
    __shared__ int    warpTot[8];
    __shared__ double sd1[32], sd2[32], sd3[32];
    __shared__ int    siw[32];
    __shared__ unsigned s_prefix;
    __shared__ int s_rem;
    __shared__ double s_ll, s_lm, s_pce;
    __shared__ int s_np, s_np1, s_hv;

    int gnum = min(gnum_arr[b], Gn);
    float w = (float)img[b * 2 + 1];
    float h = (float)img[b * 2 + 0];
    if (tid < Gn * 4)
        ((float*)str)[tid] = gtb[b * Gn * 4 + tid] / ((tid & 1) ? h : w);
    if (tid < Gn) {
        float x1 = gtb[b*Gn*4 + tid*4+0] / w, y1 = gtb[b*Gn*4 + tid*4+1] / h;
        float x2 = gtb[b*Gn*4 + tid*4+2] / w, y2 = gtb[b*Gn*4 + tid*4+3] / h;
        sa[tid] = (x2 - x1) * (y2 - y1);
        int lab = gtl[b * Gn + tid];
        if (lab == 0) lab = 1;
        if (gtlm[b * Gn * 10 + tid * 10] < 0.0f) lab = -1;
        slab[tid] = lab;
    }
    if (tid < Gn * 10)
        slm[tid] = gtlm[b * Gn * 10 + tid] / ((tid & 1) ? h : w);

    // ---- phase 1: per-gt global argmax from d_gpart (warp per gt) ----
    for (int g = wid; g < Gn; g += 32) {
        if (g < gnum) {
            unsigned long long best = 0ull;
            for (int c = lane; c < NB3; c += 32) {
                unsigned long long v = d_gpart[((size_t)b * Gn + g) * NB3 + c];
                if (v > best) best = v;
            }
            #pragma unroll
            for (int d = 16; d > 0; d >>= 1) {
                unsigned long long o = __shfl_down_sync(0xFFFFFFFFu, best, d);
                if (o > best) best = o;        // self-return harmless for max
            }
            if (lane == 0) {
                sbpi[g] = 0xFFFFFFFFu - (unsigned)best;
                svalid[g] = ((unsigned)(best >> 32) >= 0x3E4CCCCDu) ? 1 : 0;  // iou >= 0.2f
            }
        } else if (lane == 0) { sbpi[g] = 0xFFFFFFFFu; svalid[g] = 0; }
    }

    // ---- phase 2: combine k_A partials ----
    double vll = 0, vlm = 0, vpce = 0; int vnp = 0;
    if (tid < NB3) {
        int idx = b * NB3 + tid;
        vll = (double)d_part_ll[idx];
        vlm = (double)d_part_lm[idx];
        vpce = (double)d_part_pce[idx];
        vnp = d_part_np[idx];
    }
    #pragma unroll
    for (int off = 16; off > 0; off >>= 1) {
        vll  += __shfl_down_sync(0xFFFFFFFFu, vll,  off);
        vlm  += __shfl_down_sync(0xFFFFFFFFu, vlm,  off);
        vpce += __shfl_down_sync(0xFFFFFFFFu, vpce, off);
        vnp  += __shfl_down_sync(0xFFFFFFFFu, vnp,  off);
    }
    if (lane == 0) { sd1[wid] = vll; sd2[wid] = vlm; sd3[wid] = vpce; siw[wid] = vnp; }
    if (tid < 256) hist[tid] = 0;
    __syncthreads();
    if (wid == 0) {
        double a = sd1[lane], c = sd2[lane], d = sd3[lane]; int e = siw[lane];
        #pragma unroll
        for (int off = 16; off > 0; off >>= 1) {
            a += __shfl_down_sync(0xFFFFFFFFu, a, off);
            c += __shfl_down_sync(0xFFFFFFFFu, c, off);
            d += __shfl_down_sync(0xFFFFFFFFu, d, off);
            e += __shfl_down_sync(0xFFFFFFFFu, e, off);
        }
        if (lane == 0) {
            s_ll = a; s_lm = c; s_pce = d;
            s_np = e & 0xFFFF; s_np1 = e >> 16;
            s_prefix = 0u;
        }
    }
    if (tid == 32) {          // different warp from the writers above is fine pre-barrier? no: do on tid 0 post-barrier? svalid written pre-barrier by lane0s; safe to read after the barrier below
    }
    __syncthreads();
    if (tid == 0) {
        int hv = 0;
        for (int g = 0; g < gnum; g++) if (svalid[g]) hv = 1;
        s_hv = hv;
    }
    __syncthreads();

    // ---- phase 3: fix-up correction (<=48 affected priors, parallel threads) ----
    long long baseP = (long long)b * Pn;
    const float* loc_b  = loc  + baseP * 4;
    const float* conf_b = conf + baseP * 2;
    const float* lmd_b  = lmd  + baseP * 10;
    double dll = 0, dlm = 0, dpce = 0; int dnp = 0, dnp1 = 0;
    if (s_hv && tid < gnum) {
        unsigned p = sbpi[tid];
        bool first = true;
        for (int g2 = 0; g2 < tid; g2++) if (sbpi[g2] == p) first = false;
        if (first) {
            int bgf = tid, filled = svalid[tid];
            for (int g2 = tid + 1; g2 < gnum; g2++)
                if (sbpi[g2] == p) { bgf = g2; filled |= svalid[g2]; }
            // recompute k_A's raw (ov0, bg0) for this prior (identical ops)
            float4 pr = ((const float4*)priors)[p];
            float hx = pr.z * 0.5f, hy = pr.w * 0.5f;
            float4 pf; pf.x = pr.x - hx; pf.y = pr.y - hy; pf.z = pr.x + hx; pf.w = pr.y + hy;
            float pa = (pf.z - pf.x) * (pf.w - pf.y);
            float bi = -1.0f, bd = 1.0f; int bg0 = 0;
            for (int g = 0; g < gnum; g++) {
                float in_ = inter_fn(str[g], pf);
                float dn_ = sa[g] + pa - in_;
                if (in_ * bd > bi * dn_) { bi = in_; bd = dn_; bg0 = g; }
            }
            float ov0 = bi / bd;
            float ovf = filled ? 2.0f : ov0;
            Contrib o = contrib_fn((int)p, ov0, bg0, loc_b, conf_b, lmd_b, priors, str, slm, slab);
            Contrib n = contrib_fn((int)p, ovf, bgf, loc_b, conf_b, lmd_b, priors, str, slm, slab);
            dll = (double)n.ll - (double)o.ll;
            dlm = (double)n.llm - (double)o.llm;
            dpce = (double)n.pce - (double)o.pce;
            dnp = n.np - o.np; dnp1 = n.np1 - o.np1;
            d_ce[baseP + p] = n.pos ? -1.0f : n.ce;
        }
    }
    if (tid < Gn) { sdll[tid]=dll; sdlm[tid]=dlm; sdpce[tid]=dpce; sdnp[tid]=dnp; sdnp1[tid]=dnp1; }
    __syncthreads();
    if (tid == 0) {
        if (s_hv) {
            double a = 0, c = 0, d = 0; int e = 0, e1 = 0;
            for (int i = 0; i < Gn; i++) { a += sdll[i]; c += sdlm[i]; d += sdpce[i]; e += sdnp[i]; e1 += sdnp1[i]; }
            s_ll += a; s_lm += c; s_pce += d; s_np += e; s_np1 += e1;
        } else {
            s_ll = 0.0; s_lm = 0.0; s_pce = 0.0; s_np = 0; s_np1 = 0;
        }
    }
    __syncthreads();   // also orders the d_ce global fixes before the reads below

    // ---- phase 4: ce in registers + radix select (parallel crossover) ----
    float ce_r[KPT];
    #pragma unroll
    for (int k = 0; k < KPT; k++) {
        int p = tid + k * NTHB;
        ce_r[k] = (p < Pn) ? d_ce[baseP + p] : -1.0f;
    }
    int np = s_np;
    int K = min(7 * np, Pn - 1);
    int cntnon = Pn - np;
    double negsum = 0.0;   // meaningful at tid 0 only

    if (K > 0 && K >= cntnon) {
        double locs = 0.0;
        #pragma unroll
        for (int k = 0; k < KPT; k++) if (ce_r[k] >= 0.0f) locs += (double)ce_r[k];
        #pragma unroll
        for (int off = 16; off > 0; off >>= 1) locs += __shfl_down_sync(0xFFFFFFFFu, locs, off);
        if (lane == 0) sd1[wid] = locs;
        __syncthreads();
        if (wid == 0) {
            double a = sd1[lane];
            #pragma unroll
            for (int off = 16; off > 0; off >>= 1) a += __shfl_down_sync(0xFFFFFFFFu, a, off);
            if (lane == 0) negsum = a;
        }
    } else if (K > 0) {
        if (tid == 0) s_rem = K;
        __syncthreads();
        for (int shift = 24; shift >= 0; shift -= 8) {
            unsigned mask = (shift == 24) ? 0u : (0xFFFFFFFFu << (shift + 8));
            unsigned pref = s_prefix;
            int remLocal = s_rem;
            #pragma unroll
            for (int k = 0; k < KPT; k++) {
                float v = ce_r[k];
                bool valid = false; unsigned bin = 0xFFFFFFFFu;
                if (v >= 0.0f) {
                    unsigned u = __float_as_uint(v);
                    if ((u & mask) == pref) { valid = true; bin = (u >> shift) & 255u; }
                }
                unsigned mm = __match_any_sync(0xFFFFFFFFu, valid ? bin : 0xFFFFFFFFu);
                if (valid && lane == (__ffs(mm) - 1))
                    atomicAdd(&hist[bin], __popc(mm));
            }
            __syncthreads();
            int cnt = 0, sfx = 0;
            if (tid < 256) {
                cnt = hist[tid];
                hist[tid] = 0;
                sfx = cnt;
                #pragma unroll
                for (int d = 1; d < 32; d <<= 1) {
                    int o = __shfl_down_sync(0xFFFFFFFFu, sfx, d);
                    if (lane + d < 32) sfx += o;
                }
                if (lane == 0) warpTot[wid] = sfx;
            }
            __syncthreads();
            if (tid < 256) {
                int H = 0;
                #pragma unroll
                for (int w2 = 0; w2 < 8; w2++) if (w2 > wid) H += warpTot[w2];
                int Sx = sfx - cnt + H;
                if (Sx < remLocal && Sx + cnt >= remLocal) {
                    s_prefix = pref | ((unsigned)tid << shift);
                    s_rem = remLocal - Sx;
                }
            }
            __syncthreads();
        }
        unsigned T = s_prefix;
        int rem = s_rem;
        double locs = 0.0;
        #pragma unroll
        for (int k = 0; k < KPT; k++) {
            float v = ce_r[k];
            if (v >= 0.0f && __float_as_uint(v) > T) locs += (double)v;
        }
        #pragma unroll
        for (int off = 16; off > 0; off >>= 1) locs += __shfl_down_sync(0xFFFFFFFFu, locs, off);
        if (lane == 0) sd1[wid] = locs;
        __syncthreads();
        if (wid == 0) {
            double a = sd1[lane];
            #pragma unroll
            for (int off = 16; off > 0; off >>= 1) a += __shfl_down_sync(0xFFFFFFFFu, a, off);
            if (lane == 0) negsum = a + (double)rem * (double)__uint_as_float(T);
        }
    }
    if (tid == 0) {
        d_b_ll[b] = s_ll;
        d_b_lm[b] = s_lm;
        d_b_lc[b] = s_pce + negsum;
        d_b_np[b] = np;
        d_b_np1[b] = s_np1;
    }
}

// ---------------- K6: final combine ----------------
__global__ void k_final(float* __restrict__ out) {
    __shared__ double s1[Bn], s2[Bn], s3[Bn];
    __shared__ int i1[Bn], i2[Bn];
    int t = threadIdx.x;
    s1[t] = d_b_ll[t]; s2[t] = d_b_lc[t]; s3[t] = d_b_lm[t];
    i1[t] = d_b_np[t]; i2[t] = d_b_np1[t];
    __syncthreads();
    for (int s = Bn/2; s > 0; s >>= 1) {
        if (t < s) {
            s1[t] += s1[t+s]; s2[t] += s2[t+s]; s3[t] += s3[t+s];
            i1[t] += i1[t+s]; i2[t] += i2[t+s];
        }
        __syncthreads();
    }
    if (t == 0) {
        double N  = (double)(i1[0] > 0 ? i1[0] : 1);
        double N1 = (double)(i2[0] > 0 ? i2[0] : 1);
        out[0] = (float)(s1[0] / N);
        out[1] = (float)(s2[0] / N);
        out[2] = (float)(s3[0] / N1);
    }
}

// ---------------- launcher ----------------
extern "C" void kernel_launch(void* const* d_in, const int* in_sizes, int n_in,
                              void* d_out, int out_size) {
    const float* loc    = (const float*)d_in[0];
    const float* conf   = (const float*)d_in[1];
    const float* lmd    = (const float*)d_in[2];
    const float* priors = (const float*)d_in[3];
    const float* gtb    = (const float*)d_in[4];
    const int*   gtl    = (const int*)d_in[5];
    const float* gtlm   = (const float*)d_in[6];
    const int*   gnum   = (const int*)d_in[7];
    const int*   img    = (const int*)d_in[8];
    float* out = (float*)d_out;

    k_A<<<dim3(NB3, Bn), NTH>>>(gnum, priors, gtb, gtl, gtlm, img, loc, conf, lmd);
    k_batch2<<<Bn, NTHB>>>(gnum, priors, gtb, gtl, gtlm, img, loc, conf, lmd);
    k_final<<<1, Bn>>>(out);
}